// round 7
// baseline (speedup 1.0000x reference)
#include <cuda_runtime.h>
#include <cuda_bf16.h>
#include <cstdint>

#define H_FEATS 128
#define D2 256
#define LN_EPS 1e-5f
#define MAX_NODES 262144

// Node table: x=sum(h), y=sum(h^2), z=dot(h, gW[0:128]), w=dot(h, gW[128:256])
__device__ float4 g_node_tab[MAX_NODES];
__device__ float  g_Sgw;   // sum(gamma*W)
__device__ float  g_C;     // sum(beta*W) + b

// ---------------------------------------------------------------------------
// Kernel 1: per-node stats. 8 lanes per node, 4 float4 loads per lane (MLP=4).
// Each block rebuilds gW = gamma*W in smem. Block 0 also writes the two
// epilogue scalars.
// ---------------------------------------------------------------------------
__global__ void __launch_bounds__(256) node_stats_kernel(
        const float* __restrict__ h,
        const float* __restrict__ gamma,
        const float* __restrict__ beta,
        const float* __restrict__ W,
        const float* __restrict__ b,
        int n_nodes) {
    __shared__ float4 sgW[64];   // gW as 64 float4s

    int t = threadIdx.x;
    float w  = W[t];
    float gw = gamma[t] * w;
    reinterpret_cast<float*>(sgW)[t] = gw;

    if (blockIdx.x == 0) {
        __shared__ float sA[D2];
        __shared__ float sB[D2];
        sA[t] = gw;
        sB[t] = beta[t] * w;
        __syncthreads();
        #pragma unroll
        for (int off = 128; off > 0; off >>= 1) {
            if (t < off) { sA[t] += sA[t + off]; sB[t] += sB[t + off]; }
            __syncthreads();
        }
        if (t == 0) {
            g_Sgw = sA[0];
            g_C   = sB[0] + __ldg(b);
        }
    } else {
        __syncthreads();
    }

    int group = t >> 3;           // node within block (0..31)
    int sub   = t & 7;            // lane within node-group (0..7)
    int node  = blockIdx.x * 32 + group;
    if (node >= n_nodes) return;

    const float4* row = reinterpret_cast<const float4*>(h + (size_t)node * H_FEATS);
    float4 v0 = __ldg(row + sub);
    float4 v1 = __ldg(row + sub + 8);
    float4 v2 = __ldg(row + sub + 16);
    float4 v3 = __ldg(row + sub + 24);

    float4 gl0 = sgW[sub];       float4 gh0 = sgW[32 + sub];
    float4 gl1 = sgW[sub + 8];   float4 gh1 = sgW[40 + sub];
    float4 gl2 = sgW[sub + 16];  float4 gh2 = sgW[48 + sub];
    float4 gl3 = sgW[sub + 24];  float4 gh3 = sgW[56 + sub];

    float s1 = (v0.x + v0.y + v0.z + v0.w) + (v1.x + v1.y + v1.z + v1.w)
             + (v2.x + v2.y + v2.z + v2.w) + (v3.x + v3.y + v3.z + v3.w);
    float s2 = v0.x*v0.x + v0.y*v0.y + v0.z*v0.z + v0.w*v0.w
             + v1.x*v1.x + v1.y*v1.y + v1.z*v1.z + v1.w*v1.w
             + v2.x*v2.x + v2.y*v2.y + v2.z*v2.z + v2.w*v2.w
             + v3.x*v3.x + v3.y*v3.y + v3.z*v3.z + v3.w*v3.w;
    float ds = v0.x*gl0.x + v0.y*gl0.y + v0.z*gl0.z + v0.w*gl0.w
             + v1.x*gl1.x + v1.y*gl1.y + v1.z*gl1.z + v1.w*gl1.w
             + v2.x*gl2.x + v2.y*gl2.y + v2.z*gl2.z + v2.w*gl2.w
             + v3.x*gl3.x + v3.y*gl3.y + v3.z*gl3.z + v3.w*gl3.w;
    float dd = v0.x*gh0.x + v0.y*gh0.y + v0.z*gh0.z + v0.w*gh0.w
             + v1.x*gh1.x + v1.y*gh1.y + v1.z*gh1.z + v1.w*gh1.w
             + v2.x*gh2.x + v2.y*gh2.y + v2.z*gh2.z + v2.w*gh2.w
             + v3.x*gh3.x + v3.y*gh3.y + v3.z*gh3.z + v3.w*gh3.w;

    #pragma unroll
    for (int off = 4; off > 0; off >>= 1) {
        s1 += __shfl_down_sync(0xFFFFFFFFu, s1, off);
        s2 += __shfl_down_sync(0xFFFFFFFFu, s2, off);
        ds += __shfl_down_sync(0xFFFFFFFFu, ds, off);
        dd += __shfl_down_sync(0xFFFFFFFFu, dd, off);
    }
    if (sub == 0) {
        g_node_tab[node] = make_float4(s1, s2, ds, dd);
    }
}

// ---------------------------------------------------------------------------
// Kernel 2: persistent grid-stride edge kernel, 4 edges per thread per
// iteration, double-buffered index loads so the DRAM index latency of
// iteration i+1 hides behind iteration i's gathers + compute.
// ---------------------------------------------------------------------------
__global__ void __launch_bounds__(256, 4) edge_score_kernel(
        const int* __restrict__ src,
        const int* __restrict__ dst,
        float* __restrict__ out,
        int n_edges) {
    const float Sgw = g_Sgw;
    const float C   = g_C;
    const float inv = 1.0f / (float)D2;

    const int4* src4 = reinterpret_cast<const int4*>(src);
    const int4* dst4 = reinterpret_cast<const int4*>(dst);
    float4* out4 = reinterpret_cast<float4*>(out);

    int nquads = n_edges >> 2;
    int tid    = blockIdx.x * blockDim.x + threadIdx.x;
    int stride = gridDim.x * blockDim.x;

    int q = tid;
    if (q < nquads) {
        int4 s = __ldg(src4 + q);
        int4 d = __ldg(dst4 + q);
        while (true) {
            int qn = q + stride;
            bool more = qn < nquads;
            int4 sn, dn;
            if (more) {                       // prefetch next indices NOW
                sn = __ldg(src4 + qn);
                dn = __ldg(dst4 + qn);
            }

            float4 a0 = __ldg(&g_node_tab[s.x]);
            float4 c0 = __ldg(&g_node_tab[d.x]);
            float4 a1 = __ldg(&g_node_tab[s.y]);
            float4 c1 = __ldg(&g_node_tab[d.y]);
            float4 a2 = __ldg(&g_node_tab[s.z]);
            float4 c2 = __ldg(&g_node_tab[d.z]);
            float4 a3 = __ldg(&g_node_tab[s.w]);
            float4 c3 = __ldg(&g_node_tab[d.w]);

            float4 r;
            {
                float mu  = (a0.x + c0.x) * inv;
                float var = fmaf(-mu, mu, (a0.y + c0.y) * inv);
                r.x = fmaf(rsqrtf(var + LN_EPS), fmaf(-mu, Sgw, a0.z + c0.w), C);
            }
            {
                float mu  = (a1.x + c1.x) * inv;
                float var = fmaf(-mu, mu, (a1.y + c1.y) * inv);
                r.y = fmaf(rsqrtf(var + LN_EPS), fmaf(-mu, Sgw, a1.z + c1.w), C);
            }
            {
                float mu  = (a2.x + c2.x) * inv;
                float var = fmaf(-mu, mu, (a2.y + c2.y) * inv);
                r.z = fmaf(rsqrtf(var + LN_EPS), fmaf(-mu, Sgw, a2.z + c2.w), C);
            }
            {
                float mu  = (a3.x + c3.x) * inv;
                float var = fmaf(-mu, mu, (a3.y + c3.y) * inv);
                r.w = fmaf(rsqrtf(var + LN_EPS), fmaf(-mu, Sgw, a3.z + c3.w), C);
            }
            out4[q] = r;

            if (!more) break;
            q = qn; s = sn; d = dn;
        }
    }

    // tail (n_edges not divisible by 4)
    for (int i = (nquads << 2) + tid; i < n_edges; i += stride) {
        float4 a = __ldg(&g_node_tab[src[i]]);
        float4 c = __ldg(&g_node_tab[dst[i]]);
        float mu  = (a.x + c.x) * inv;
        float var = fmaf(-mu, mu, (a.y + c.y) * inv);
        out[i] = fmaf(rsqrtf(var + LN_EPS), fmaf(-mu, Sgw, a.z + c.w), C);
    }
}

// ---------------------------------------------------------------------------
// Launch
// Inputs: 0=h [N*128] f32, 1=src [E] i32, 2=dst [E] i32,
//         3=ln_gamma [256] f32, 4=ln_beta [256] f32, 5=W [256] f32, 6=b [1] f32
// Output: [E] f32
// ---------------------------------------------------------------------------
extern "C" void kernel_launch(void* const* d_in, const int* in_sizes, int n_in,
                              void* d_out, int out_size) {
    const float* h     = (const float*)d_in[0];
    const int*   src   = (const int*)d_in[1];
    const int*   dst   = (const int*)d_in[2];
    const float* gamma = (const float*)d_in[3];
    const float* beta  = (const float*)d_in[4];
    const float* W     = (const float*)d_in[5];
    const float* b     = (const float*)d_in[6];
    float* out = (float*)d_out;

    int n_nodes = in_sizes[0] / H_FEATS;
    int n_edges = in_sizes[1];

    // 32 nodes per block (8 lanes per node)
    int nblocks = (n_nodes + 31) / 32;
    node_stats_kernel<<<nblocks, 256>>>(h, gamma, beta, W, b, n_nodes);

    // persistent: 4 blocks per SM (152 SMs on GB300) -> ~2.6 quads/thread
    int eblocks = 152 * 4;
    edge_score_kernel<<<eblocks, 256>>>(src, dst, out, n_edges);
}

// round 9
// speedup vs baseline: 1.0282x; 1.0282x over previous
#include <cuda_runtime.h>
#include <cuda_bf16.h>
#include <cstdint>

#define H_FEATS 128
#define D2 256
#define LN_EPS 1e-5f
#define MAX_NODES 262144

// Node table: x=sum(h), y=sum(h^2), z=dot(h, gW[0:128]), w=dot(h, gW[128:256])
__device__ float4 g_node_tab[MAX_NODES];
__device__ float  g_Sgw;      // sum(gamma*W)
__device__ float  g_C;        // sum(beta*W) + b
__device__ int    g_arrive;   // barrier arrival counter (releaser resets to 0)
__device__ int    g_phase;    // barrier sense (alternates across runs; any init ok)

// ---------------------------------------------------------------------------
// Persistent fused kernel. Grid is sized by the host to be fully co-resident,
// so the software grid barrier cannot deadlock. Phase 1: grid-stride node
// stats (32 nodes/block-iter, 8 lanes/node, MLP=4). Barrier. Phase 2:
// grid-stride edge scoring (4 edges/thread-iter).
// ---------------------------------------------------------------------------
__global__ void __launch_bounds__(256) fused_kernel(
        const float* __restrict__ h,
        const int*   __restrict__ src,
        const int*   __restrict__ dst,
        const float* __restrict__ gamma,
        const float* __restrict__ beta,
        const float* __restrict__ W,
        const float* __restrict__ b,
        float*       __restrict__ out,
        int n_nodes, int n_edges) {
    int t = threadIdx.x;

    // Read barrier sense BEFORE any arrival can flip it (flip requires all
    // blocks to arrive, which happens after every block has executed this).
    int my_phase = *(volatile int*)&g_phase;

    // ------------------------- NODE PHASE (grid-stride) -------------------
    __shared__ float4 sgW[64];   // gW as 64 float4s
    {
        float w  = W[t];
        float gw = gamma[t] * w;
        reinterpret_cast<float*>(sgW)[t] = gw;

        if (blockIdx.x == 0) {
            __shared__ float sA[D2];
            __shared__ float sB[D2];
            sA[t] = gw;
            sB[t] = beta[t] * w;
            __syncthreads();
            #pragma unroll
            for (int off = 128; off > 0; off >>= 1) {
                if (t < off) { sA[t] += sA[t + off]; sB[t] += sB[t + off]; }
                __syncthreads();
            }
            if (t == 0) {
                g_Sgw = sA[0];
                g_C   = sB[0] + __ldg(b);
            }
        } else {
            __syncthreads();
        }
    }

    int group = t >> 3;           // node slot within block (0..31)
    int sub   = t & 7;            // lane within node-group (0..7)
    int n_node_iters = (n_nodes + 31) >> 5;   // node-groups of 32 per block-iter

    float4 gl0 = sgW[sub];       float4 gh0 = sgW[32 + sub];
    float4 gl1 = sgW[sub + 8];   float4 gh1 = sgW[40 + sub];
    float4 gl2 = sgW[sub + 16];  float4 gh2 = sgW[48 + sub];
    float4 gl3 = sgW[sub + 24];  float4 gh3 = sgW[56 + sub];

    for (int nb = blockIdx.x; nb < n_node_iters; nb += gridDim.x) {
        int node = nb * 32 + group;
        if (node >= n_nodes) continue;

        const float4* row = reinterpret_cast<const float4*>(h + (size_t)node * H_FEATS);
        float4 v0 = __ldg(row + sub);
        float4 v1 = __ldg(row + sub + 8);
        float4 v2 = __ldg(row + sub + 16);
        float4 v3 = __ldg(row + sub + 24);

        float s1 = (v0.x + v0.y + v0.z + v0.w) + (v1.x + v1.y + v1.z + v1.w)
                 + (v2.x + v2.y + v2.z + v2.w) + (v3.x + v3.y + v3.z + v3.w);
        float s2 = v0.x*v0.x + v0.y*v0.y + v0.z*v0.z + v0.w*v0.w
                 + v1.x*v1.x + v1.y*v1.y + v1.z*v1.z + v1.w*v1.w
                 + v2.x*v2.x + v2.y*v2.y + v2.z*v2.z + v2.w*v2.w
                 + v3.x*v3.x + v3.y*v3.y + v3.z*v3.z + v3.w*v3.w;
        float ds = v0.x*gl0.x + v0.y*gl0.y + v0.z*gl0.z + v0.w*gl0.w
                 + v1.x*gl1.x + v1.y*gl1.y + v1.z*gl1.z + v1.w*gl1.w
                 + v2.x*gl2.x + v2.y*gl2.y + v2.z*gl2.z + v2.w*gl2.w
                 + v3.x*gl3.x + v3.y*gl3.y + v3.z*gl3.z + v3.w*gl3.w;
        float dd = v0.x*gh0.x + v0.y*gh0.y + v0.z*gh0.z + v0.w*gh0.w
                 + v1.x*gh1.x + v1.y*gh1.y + v1.z*gh1.z + v1.w*gh1.w
                 + v2.x*gh2.x + v2.y*gh2.y + v2.z*gh2.z + v2.w*gh2.w
                 + v3.x*gh3.x + v3.y*gh3.y + v3.z*gh3.z + v3.w*gh3.w;

        #pragma unroll
        for (int off = 4; off > 0; off >>= 1) {
            s1 += __shfl_down_sync(0xFFFFFFFFu, s1, off);
            s2 += __shfl_down_sync(0xFFFFFFFFu, s2, off);
            ds += __shfl_down_sync(0xFFFFFFFFu, ds, off);
            dd += __shfl_down_sync(0xFFFFFFFFu, dd, off);
        }
        if (sub == 0) {
            g_node_tab[node] = make_float4(s1, s2, ds, dd);
        }
    }

    // ------------------- GRID BARRIER (sense-reversing) --------------------
    __syncthreads();
    if (t == 0) {
        __threadfence();                               // publish table stores
        int ticket = atomicAdd(&g_arrive, 1);
        if (ticket == (int)gridDim.x - 1) {
            g_arrive = 0;                              // reset for next run
            __threadfence();
            atomicExch(&g_phase, my_phase ^ 1);        // release
        } else {
            while (*(volatile int*)&g_phase == my_phase) {
                __nanosleep(32);
            }
        }
        __threadfence();                               // acquire
    }
    __syncthreads();

    // ------------------------- EDGE PHASE (grid-stride) --------------------
    const float Sgw = g_Sgw;
    const float C   = g_C;
    const float inv = 1.0f / (float)D2;

    const int4* src4 = reinterpret_cast<const int4*>(src);
    const int4* dst4 = reinterpret_cast<const int4*>(dst);
    float4* out4 = reinterpret_cast<float4*>(out);

    int nquads = n_edges >> 2;
    int gid    = blockIdx.x * blockDim.x + t;
    int stride = gridDim.x * blockDim.x;

    for (int q = gid; q < nquads; q += stride) {
        int4 s4 = __ldg(src4 + q);
        int4 d4 = __ldg(dst4 + q);

        float4 a0 = __ldg(&g_node_tab[s4.x]);
        float4 c0 = __ldg(&g_node_tab[d4.x]);
        float4 a1 = __ldg(&g_node_tab[s4.y]);
        float4 c1 = __ldg(&g_node_tab[d4.y]);
        float4 a2 = __ldg(&g_node_tab[s4.z]);
        float4 c2 = __ldg(&g_node_tab[d4.z]);
        float4 a3 = __ldg(&g_node_tab[s4.w]);
        float4 c3 = __ldg(&g_node_tab[d4.w]);

        float4 r;
        {
            float mu  = (a0.x + c0.x) * inv;
            float var = fmaf(-mu, mu, (a0.y + c0.y) * inv);
            r.x = fmaf(rsqrtf(var + LN_EPS), fmaf(-mu, Sgw, a0.z + c0.w), C);
        }
        {
            float mu  = (a1.x + c1.x) * inv;
            float var = fmaf(-mu, mu, (a1.y + c1.y) * inv);
            r.y = fmaf(rsqrtf(var + LN_EPS), fmaf(-mu, Sgw, a1.z + c1.w), C);
        }
        {
            float mu  = (a2.x + c2.x) * inv;
            float var = fmaf(-mu, mu, (a2.y + c2.y) * inv);
            r.z = fmaf(rsqrtf(var + LN_EPS), fmaf(-mu, Sgw, a2.z + c2.w), C);
        }
        {
            float mu  = (a3.x + c3.x) * inv;
            float var = fmaf(-mu, mu, (a3.y + c3.y) * inv);
            r.w = fmaf(rsqrtf(var + LN_EPS), fmaf(-mu, Sgw, a3.z + c3.w), C);
        }
        out4[q] = r;
    }

    // tail edges (n_edges % 4): first threads of block 0
    if (blockIdx.x == 0) {
        int i = (nquads << 2) + t;
        if (i < n_edges) {
            float4 a = __ldg(&g_node_tab[src[i]]);
            float4 c = __ldg(&g_node_tab[dst[i]]);
            float mu  = (a.x + c.x) * inv;
            float var = fmaf(-mu, mu, (a.y + c.y) * inv);
            out[i] = fmaf(rsqrtf(var + LN_EPS), fmaf(-mu, Sgw, a.z + c.w), C);
        }
    }
}

// ---------------------------------------------------------------------------
// Launch
// Inputs: 0=h [N*128] f32, 1=src [E] i32, 2=dst [E] i32,
//         3=ln_gamma [256] f32, 4=ln_beta [256] f32, 5=W [256] f32, 6=b [1] f32
// Output: [E] f32
// ---------------------------------------------------------------------------
extern "C" void kernel_launch(void* const* d_in, const int* in_sizes, int n_in,
                              void* d_out, int out_size) {
    const float* h     = (const float*)d_in[0];
    const int*   src   = (const int*)d_in[1];
    const int*   dst   = (const int*)d_in[2];
    const float* gamma = (const float*)d_in[3];
    const float* beta  = (const float*)d_in[4];
    const float* W     = (const float*)d_in[5];
    const float* b     = (const float*)d_in[6];
    float* out = (float*)d_out;

    int n_nodes = in_sizes[0] / H_FEATS;
    int n_edges = in_sizes[1];

    // Grid sized for guaranteed full co-residency -> barrier is deadlock-free.
    int dev = 0, sms = 148, occ = 0;
    cudaGetDevice(&dev);
    cudaDeviceGetAttribute(&sms, cudaDevAttrMultiProcessorCount, dev);
    cudaOccupancyMaxActiveBlocksPerMultiprocessor(&occ, fused_kernel, 256, 0);
    if (occ < 1) occ = 1;
    int grid = sms * occ;

    fused_kernel<<<grid, 256>>>(h, src, dst, gamma, beta, W, b, out,
                                n_nodes, n_edges);
}